// round 16
// baseline (speedup 1.0000x reference)
#include <cuda_runtime.h>
#include <cuda_bf16.h>
#include <math.h>

#define BB 64
#define TT 512
#define SS 512
#define NC 64
#define AT 128
#define NN 128
#define NBLK 128
#define NTHR 512

// ---------------- persistent scratch (device globals; no allocation) ----------------
__device__ __align__(256) float g_psiT[(size_t)BB * AT * TT];  // [b][a][t] 16.8 MB
__device__ __align__(256) float g_h1[2][BB * SS];
__device__ __align__(256) float g_h2[2][BB * SS];
__device__ __align__(256) float g_ctx[2][BB * SS];
__device__ unsigned g_bar_count = 0;
__device__ unsigned g_bar_gen = 0;

__device__ __forceinline__ float sigf(float v) { return 1.0f / (1.0f + expf(-v)); }

// ---------------- smem layout (floats) ----------------
#define OFF_W0   0            // 16 x 1028  (rows: [0..511]=src A, [512..1023]=src B)
#define OFF_W1   16448        // 16 x 1028
#define OFF_E    32896        // 16 x 64    (Wih0 one-hot cols for this block's rows)
#define OFF_WCD  33920        // 1024       (blocks 64..127: Wcd row)
#define OFF_B0   34944        // 16
#define OFF_B1   34960        // 16
#define OFF_DYN  34976
// LSTM phase view of dynamic region:
#define OFF_ACT  OFF_DYN              // 2 teams x 2 bufs x (64 x 68) = 17408
#define OFF_G    (OFF_DYN + 17408)    // 2 x 16 x 68 = 2176
// ATTN phase view of dynamic region:
#define OFF_H2S  OFF_DYN              // 512
#define OFF_PHI  (OFF_DYN + 512)      // 128
#define OFF_EX   (OFF_DYN + 640)      // 512
#define OFF_RED  (OFF_DYN + 1152)     // 32
#define OFF_CTXP (OFF_DYN + 1184)     // 512
#define SMEM_FLOATS (OFF_DYN + 17408 + 2176)
#define SMEM_BYTES (SMEM_FLOATS * 4)  // 218240

// ---------------- grid barrier (all 128 blocks co-resident, 1 block/SM) ----------------
__device__ __forceinline__ void grid_barrier() {
    __syncthreads();
    if (threadIdx.x == 0) {
        unsigned old = *(volatile unsigned*)&g_bar_gen;
        __threadfence();
        unsigned t = atomicAdd(&g_bar_count, 1u);
        if (t == NBLK - 1) {
            g_bar_count = 0;
            __threadfence();
            *(volatile unsigned*)&g_bar_gen = old + 1;
        } else {
            while (*(volatile unsigned*)&g_bar_gen == old) __nanosleep(32);
        }
        __threadfence();
    }
    __syncthreads();
}

__device__ __forceinline__ void cp16(float* sp, const float* gp) {
    unsigned s = (unsigned)__cvta_generic_to_shared(sp);
    asm volatile("cp.async.cg.shared.global [%0], [%1], 16;" :: "r"(s), "l"(gp));
}

// stage one [64 b][64 k] act chunk (16 KB) with 256 team-threads
__device__ __forceinline__ void stage_chunk(float* buf, const float* act, int kc, int ttid) {
    #pragma unroll
    for (int i = 0; i < 4; i++) {
        int u = ttid + 256 * i;            // 0..1023
        int b = u >> 4, k4 = (u & 15) * 4;
        cp16(buf + b * 68 + k4, act + b * SS + kc + k4);
    }
    asm volatile("cp.async.commit_group;");
}

// ---------------- one LSTM layer: team-split GEMM (K=512 per team) + fused cell ----------------
// Block tile: 16 gate-rows (4 gates x 4 d, d = bid*4 + dr) x 64 batches.
// Team t (256 thr) handles source t; thread: row rr = ttid&15, batches b0..b0+3.
template <bool ONEHOT>
__device__ void lstm_phase(float* sm, int team, int ttid, const float* sW, const float* sB,
                           const float* actS, float* hout, float& c_reg,
                           const int* xin, int step, int bid, int tid)
{
    float* tbuf = sm + OFF_ACT + team * 8704;
    float* sG   = sm + OFF_G;

    stage_chunk(tbuf, actS, 0, ttid);

    const int rr = ttid & 15, b0 = (ttid >> 4) * 4;
    const float* wbase = sW + rr * 1028 + team * 512;
    unsigned long long acc[4] = {0ull, 0ull, 0ull, 0ull};

    for (int c = 0; c < 8; c++) {
        if (c < 7) {
            stage_chunk(tbuf + ((c + 1) & 1) * 4352, actS, (c + 1) * 64, ttid);
            asm volatile("cp.async.wait_group 1;");
        } else {
            asm volatile("cp.async.wait_group 0;");
        }
        __syncthreads();

        const float* wrow = wbase + c * 64;
        const float* ab   = tbuf + (c & 1) * 4352;
        #pragma unroll
        for (int k = 0; k < 64; k += 4) {
            ulonglong2 wv = *(const ulonglong2*)(wrow + k);
            #pragma unroll
            for (int j = 0; j < 4; j++) {
                ulonglong2 av = *(const ulonglong2*)(ab + (b0 + j) * 68 + k);
                asm("fma.rn.f32x2 %0, %1, %2, %0;" : "+l"(acc[j]) : "l"(av.x), "l"(wv.x));
                asm("fma.rn.f32x2 %0, %1, %2, %0;" : "+l"(acc[j]) : "l"(av.y), "l"(wv.y));
            }
        }
        __syncthreads();
    }

    #pragma unroll
    for (int j = 0; j < 4; j++) {
        unsigned long long v = acc[j];
        float2 f = *reinterpret_cast<float2*>(&v);
        sG[team * 1088 + rr * 68 + b0 + j] = f.x + f.y;
    }
    __syncthreads();

    // cell epilogue on first 256 threads: dd = tid>>6 (0..3), b = tid&63
    if (tid < 256) {
        const int dd = tid >> 6, b = tid & 63;
        float gi = sG[(dd)      * 68 + b] + sG[1088 + (dd)      * 68 + b] + sB[dd];
        float gf = sG[(4 + dd)  * 68 + b] + sG[1088 + (4 + dd)  * 68 + b] + sB[4 + dd];
        float gg = sG[(8 + dd)  * 68 + b] + sG[1088 + (8 + dd)  * 68 + b] + sB[8 + dd];
        float go = sG[(12 + dd) * 68 + b] + sG[1088 + (12 + dd) * 68 + b] + sB[12 + dd];
        if (ONEHOT) {
            int col = xin[b * NN + step];
            gi += sm[OFF_E + (dd)      * 64 + col];
            gf += sm[OFF_E + (4 + dd)  * 64 + col];
            gg += sm[OFF_E + (8 + dd)  * 64 + col];
            go += sm[OFF_E + (12 + dd) * 64 + col];
        }
        float cn = sigf(gf) * c_reg + sigf(gi) * tanhf(gg);
        c_reg = cn;
        hout[b * SS + bid * 4 + dd] = sigf(go) * tanhf(cn);
    }
}

// ---------------- attention, d-split: block pair (b, b+64) handles batch b ----------------
__device__ void attn_phase(float* sm, const float* h, const float* Wphi, const float* bphi,
                           int parN, int b, int dhalf, int tid)
{
    const int lane = tid & 31, wid = tid >> 5;
    float* s_red = sm + OFF_RED;

    sm[OFF_H2S + tid] = g_h2[parN][b * SS + tid];
    __syncthreads();

    // phi: 4 threads per a (128 a)
    {
        int a = tid >> 2, q = tid & 3;
        const float4* w4 = (const float4*)(Wphi + (size_t)a * SS) + q * 32;
        const float4* h4 = (const float4*)(sm + OFF_H2S) + q * 32;
        float p = 0.f;
        #pragma unroll 8
        for (int i = 0; i < 32; i++) {
            float4 w = w4[i], v = h4[i];
            p += w.x * v.x + w.y * v.y + w.z * v.z + w.w * v.w;
        }
        p += __shfl_xor_sync(0xffffffffu, p, 1);
        p += __shfl_xor_sync(0xffffffffu, p, 2);
        if (q == 0) sm[OFF_PHI + a] = p + bphi[a];
    }
    __syncthreads();

    // e[t], t = tid (coalesced 128B lines from psiT)
    const float* pT = g_psiT + (size_t)b * AT * TT + tid;
    float e = 0.f;
    #pragma unroll 8
    for (int a = 0; a < AT; a++) e += sm[OFF_PHI + a] * pT[(size_t)a * TT];

    // block max over 512 threads
    float m = e;
    #pragma unroll
    for (int off = 16; off; off >>= 1) m = fmaxf(m, __shfl_xor_sync(0xffffffffu, m, off));
    if (lane == 0) s_red[wid] = m;
    __syncthreads();
    if (tid < 32) {
        float v = (lane < 16) ? s_red[lane] : -1e30f;
        #pragma unroll
        for (int off = 8; off; off >>= 1) v = fmaxf(v, __shfl_xor_sync(0xffffffffu, v, off));
        if (lane == 0) s_red[0] = v;
    }
    __syncthreads();
    float M = s_red[0];
    __syncthreads();

    float ex = expf(e - M);
    sm[OFF_EX + tid] = ex;
    float s = ex;
    #pragma unroll
    for (int off = 16; off; off >>= 1) s += __shfl_xor_sync(0xffffffffu, s, off);
    if (lane == 0) s_red[wid] = s;
    __syncthreads();
    if (tid < 32) {
        float v = (lane < 16) ? s_red[lane] : 0.f;
        #pragma unroll
        for (int off = 8; off; off >>= 1) v += __shfl_xor_sync(0xffffffffu, v, off);
        if (lane == 0) s_red[0] = v;
    }
    __syncthreads();
    float invS = 1.0f / s_red[0];

    // ctx half: th = tid>>8 sums its 256 t's for d = dhalf*256 + (tid&255)
    const int th = tid >> 8, dl = tid & 255;
    const float* hb = h + (size_t)b * TT * SS + dhalf * 256 + dl + (size_t)th * 256 * SS;
    float acc = 0.f;
    #pragma unroll 8
    for (int t2 = 0; t2 < 256; t2++)
        acc += sm[OFF_EX + th * 256 + t2] * hb[(size_t)t2 * SS];
    sm[OFF_CTXP + th * 256 + dl] = acc;
    __syncthreads();
    if (tid < 256)
        g_ctx[parN][b * SS + dhalf * 256 + tid] =
            (sm[OFF_CTXP + tid] + sm[OFF_CTXP + 256 + tid]) * invS;
}

// ---------------- class projection for step s_done (blocks 64..127, c = bid-64) ----------------
__device__ void proj_phase(float* sm, int s_done, float bcd_c, float* out, int bid, int tid)
{
    if (tid >= 256) return;
    int par = (s_done + 1) & 1;     // buffers written at step s_done
    const float* h2r = g_h2[par];
    const float* ctr = g_ctx[par];
    int c = bid - 64;
    int b = tid >> 2, p = tid & 3;
    const float* src = ((p < 2) ? h2r : ctr) + b * SS + (p & 1) * 256;
    const float* w = sm + OFF_WCD + (p >> 1) * 512 + (p & 1) * 256;
    float acc = 0.f;
    #pragma unroll 8
    for (int i = 0; i < 64; i++) {
        float4 sv = *(const float4*)(src + 4 * i);
        float4 wv = *(const float4*)(w + 4 * i);
        acc += sv.x * wv.x + sv.y * wv.y + sv.z * wv.z + sv.w * wv.w;
    }
    acc += __shfl_xor_sync(0xffffffffu, acc, 1);
    acc += __shfl_xor_sync(0xffffffffu, acc, 2);
    if (p == 0)
        out[((size_t)b * NN + s_done) * NC + c] = acc + bcd_c;
}

// ---------------- init: ctx = h[:,0,:], zero states ----------------
__global__ void init_kernel(const float* __restrict__ h)
{
    int idx = blockIdx.x * blockDim.x + threadIdx.x;   // 0..32767
    if (idx < BB * SS) {
        int b = idx >> 9, d = idx & 511;
        g_ctx[0][idx] = h[(size_t)b * TT * SS + d];
        g_h1[0][idx] = 0.f;
        g_h2[0][idx] = 0.f;
    }
}

// ---------------- psi precompute (transposed) ----------------
__global__ void __launch_bounds__(128) psi_kernel(const float* __restrict__ h,
                                                  const float* __restrict__ Wpsi,
                                                  const float* __restrict__ bpsi)
{
    __shared__ float4 s_hr[16][128];
    const int tid = threadIdx.x;
    const int r0 = blockIdx.x * 16;
    #pragma unroll
    for (int i = 0; i < 16; i++) {
        int f = tid + 128 * i;
        int r = f >> 7, c = f & 127;
        s_hr[r][c] = ((const float4*)(h + (size_t)(r0 + r) * SS))[c];
    }
    __syncthreads();
    float acc[16];
    #pragma unroll
    for (int r = 0; r < 16; r++) acc[r] = 0.f;
    const float4* wr = (const float4*)(Wpsi + (size_t)tid * SS);
    for (int k = 0; k < 128; k++) {
        float4 w = wr[k];
        #pragma unroll
        for (int r = 0; r < 16; r++) {
            float4 v = s_hr[r][k];
            acc[r] += w.x * v.x + w.y * v.y + w.z * v.z + w.w * v.w;
        }
    }
    float bp = bpsi[tid];
    #pragma unroll
    for (int r = 0; r < 16; r++) {
        int row = r0 + r;
        int b = row >> 9, t = row & 511;
        g_psiT[((size_t)b * AT + tid) * TT + t] = acc[r] + bp;
    }
}

// ---------------- the persistent kernel ----------------
__global__ void __launch_bounds__(NTHR, 1) speller_persistent(
    const int* __restrict__ xin, const float* __restrict__ h,
    const float* __restrict__ Wih0, const float* __restrict__ Whh0,
    const float* __restrict__ bih0, const float* __restrict__ bhh0,
    const float* __restrict__ Wih1, const float* __restrict__ Whh1,
    const float* __restrict__ bih1, const float* __restrict__ bhh1,
    const float* __restrict__ Wphi, const float* __restrict__ bphi,
    const float* __restrict__ Wcd,  const float* __restrict__ bcd,
    float* __restrict__ out)
{
    extern __shared__ float sm[];
    const int bid = blockIdx.x, tid = threadIdx.x;
    const int team = tid >> 8, ttid = tid & 255;

    // ---- load block-resident weights into smem (once) ----
    for (int idx = tid; idx < 16 * 512; idx += NTHR) {
        int rr = idx >> 9, k = idx & 511;
        int row = (rr >> 2) * 512 + bid * 4 + (rr & 3);
        sm[OFF_W0 + rr * 1028 + k]       = Wih0[(size_t)row * 576 + 64 + k];
        sm[OFF_W0 + rr * 1028 + 512 + k] = Whh0[(size_t)row * 512 + k];
        sm[OFF_W1 + rr * 1028 + k]       = Wih1[(size_t)row * 512 + k];
        sm[OFF_W1 + rr * 1028 + 512 + k] = Whh1[(size_t)row * 512 + k];
    }
    for (int idx = tid; idx < 16 * 64; idx += NTHR) {
        int rr = idx >> 6, cc = idx & 63;
        int row = (rr >> 2) * 512 + bid * 4 + (rr & 3);
        sm[OFF_E + idx] = Wih0[(size_t)row * 576 + cc];
    }
    if (bid >= 64) {
        int c = bid - 64;
        for (int k = tid; k < 1024; k += NTHR)
            sm[OFF_WCD + k] = Wcd[(size_t)c * 1024 + k];
    }
    if (tid < 16) {
        int row = (tid >> 2) * 512 + bid * 4 + (tid & 3);
        sm[OFF_B0 + tid] = bih0[row] + bhh0[row];
        sm[OFF_B1 + tid] = bih1[row] + bhh1[row];
    }
    float bcd_c = (bid >= 64) ? bcd[bid - 64] : 0.f;
    float c1 = 0.f, c2 = 0.f;
    __syncthreads();

    const int b_att = bid & 63, dhalf = bid >> 6;

    for (int s = 0; s < NN; s++) {
        int par = s & 1;
        {   // LSTM0: sources ctx[par], h1[par] -> h1[par^1]
            const float* actS = (team == 0) ? g_ctx[par] : g_h1[par];
            lstm_phase<true>(sm, team, ttid, sm + OFF_W0, sm + OFF_B0,
                             actS, g_h1[par ^ 1], c1, xin, s, bid, tid);
        }
        grid_barrier();
        {   // LSTM1: sources h1[par^1], h2[par] -> h2[par^1]
            const float* actS = (team == 0) ? g_h1[par ^ 1] : g_h2[par];
            lstm_phase<false>(sm, team, ttid, sm + OFF_W1, sm + OFF_B1,
                              actS, g_h2[par ^ 1], c2, xin, s, bid, tid);
        }
        grid_barrier();
        if (bid >= 64 && s > 0) proj_phase(sm, s - 1, bcd_c, out, bid, tid);
        attn_phase(sm, h, Wphi, bphi, par ^ 1, b_att, dhalf, tid);
        grid_barrier();
    }
    if (bid >= 64) proj_phase(sm, NN - 1, bcd_c, out, bid, tid);
}

// ---------------- host launcher ----------------
extern "C" void kernel_launch(void* const* d_in, const int* in_sizes, int n_in,
                              void* d_out, int out_size)
{
    const int*   x    = (const int*)  d_in[0];
    const float* h    = (const float*)d_in[1];
    const float* Wih0 = (const float*)d_in[2];
    const float* Whh0 = (const float*)d_in[3];
    const float* bih0 = (const float*)d_in[4];
    const float* bhh0 = (const float*)d_in[5];
    const float* Wih1 = (const float*)d_in[6];
    const float* Whh1 = (const float*)d_in[7];
    const float* bih1 = (const float*)d_in[8];
    const float* bhh1 = (const float*)d_in[9];
    const float* Wphi = (const float*)d_in[10];
    const float* bphi = (const float*)d_in[11];
    const float* Wpsi = (const float*)d_in[12];
    const float* bpsi = (const float*)d_in[13];
    const float* Wcd  = (const float*)d_in[14];
    const float* bcd  = (const float*)d_in[15];
    float* out = (float*)d_out;

    cudaFuncSetAttribute(speller_persistent,
                         cudaFuncAttributeMaxDynamicSharedMemorySize, SMEM_BYTES);

    init_kernel<<<128, 256>>>(h);
    psi_kernel<<<(BB * TT) / 16, 128>>>(h, Wpsi, bpsi);
    speller_persistent<<<NBLK, NTHR, SMEM_BYTES>>>(
        x, h, Wih0, Whh0, bih0, bhh0, Wih1, Whh1, bih1, bhh1,
        Wphi, bphi, Wcd, bcd, out);
}